// round 11
// baseline (speedup 1.0000x reference)
#include <cuda_runtime.h>

#define EPSF 1e-6f
#define FULLM 0xffffffffu

constexpr int cV = 128, cK = 32, cC = 256;
constexpr int cL = 4, cN = 4096, cF = 16;
constexpr int cE = 8192, cB = 512;
constexpr int cB4 = cB / 4;            // 128 float4 groups per row
constexpr int NT   = 512;
constexpr int BPSM = 2;                // blocks/SM via launch_bounds (64-reg budget)
constexpr int GRID = 148 * BPSM;       // 296 persistent blocks
constexpr int NWARP = GRID * NT / 32;  // 4736 warps
constexpr float LN2F = 0.69314718055994530942f;

// ---- scratch (static __device__ per allocation rules) ----
__device__ __align__(16) float d_lwin[cV * cK * cC];   // 4 MB (log2 domain)
__device__ __align__(16) int2  d_pw[cL * cN * cF];     // 2 MB {e*cB4, W linear}
__device__ __align__(16) float d_R[cN];                // 16 KB linear root weights
__device__ __align__(16) int   d_xT[cV * cB];          // 256 KB transposed inputs
__device__ __align__(16) float d_nmA[cN * cB];         // 8 MB
__device__ __align__(16) float d_nmB[cN * cB];         // 8 MB
__device__ __align__(16) float d_em[cE * cB];          // 16 MB

// ---- grid barrier state ----
__device__ unsigned d_bar_count = 0;
__device__ volatile unsigned d_bar_gen = 0;

// ---- single-instruction MUFU ops ----
__device__ __forceinline__ float ex2(float x) {
    float y; asm("ex2.approx.ftz.f32 %0, %1;" : "=f"(y) : "f"(x)); return y;
}
__device__ __forceinline__ float lg2(float x) {
    float y; asm("lg2.approx.ftz.f32 %0, %1;" : "=f"(y) : "f"(x)); return y;
}

// ==================================================================
// PREP: lwin (log2-normalized), packed sum tables {e*cB4, W linear},
// linear root weights, input transpose.
// ==================================================================
__global__ void __launch_bounds__(256) k_prep(const float* __restrict__ ip,
                                              const float* __restrict__ sp,
                                              const float* __restrict__ rp,
                                              const int*   __restrict__ inputs,
                                              const int*   __restrict__ sci) {
    int b = blockIdx.x;
    if (b < 512) {
        int w    = b * 8 + (threadIdx.x >> 5);
        int lane = threadIdx.x & 31;
        const float* row = ip + w * cC;
        float v[8];
        float m = -1e30f;
#pragma unroll
        for (int i = 0; i < 8; i++) {
            v[i] = lg2(row[lane + i * 32] + EPSF);
            m    = fmaxf(m, v[i]);
        }
#pragma unroll
        for (int o = 16; o; o >>= 1) m = fmaxf(m, __shfl_xor_sync(FULLM, m, o));
        float s = 0.f;
#pragma unroll
        for (int i = 0; i < 8; i++) s += ex2(v[i] - m);
#pragma unroll
        for (int o = 16; o; o >>= 1) s += __shfl_xor_sync(FULLM, s, o);
        float lse = m + lg2(s);
#pragma unroll
        for (int i = 0; i < 8; i++) d_lwin[w * cC + lane + i * 32] = v[i] - lse;
    } else if (b < 576) {
        // --- packed sum tables: one thread per (l,n) ---
        int r = (b - 512) * 256 + threadIdx.x;
        const float* spr  = sp  + r * cF;
        const int*   scir = sci + r * cF;
        float w[cF];
        float tot = 0.f;
#pragma unroll
        for (int f = 0; f < cF; f++) { w[f] = spr[f] + EPSF; tot += w[f]; }
        float inv = 1.f / tot;
        int2* dst = d_pw + r * cF;
#pragma unroll
        for (int f = 0; f < cF; f++)
            dst[f] = make_int2(scir[f] * cB4, __float_as_int(w[f] * inv));
    } else if (b == 576) {
        __shared__ float red[256];
        int t = threadIdx.x;
        float v[16];
        float s = 0.f;
#pragma unroll
        for (int i = 0; i < 16; i++) {
            v[i] = rp[t + i * 256] + EPSF;
            s += v[i];
        }
        red[t] = s;
        __syncthreads();
        for (int o = 128; o; o >>= 1) {
            if (t < o) red[t] += red[t + o];
            __syncthreads();
        }
        float inv = 1.f / red[0];
#pragma unroll
        for (int i = 0; i < 16; i++) d_R[t + i * 256] = v[i] * inv;
    } else {
        int id = (b - 577) * 256 + threadIdx.x;
        for (int i = id; i < cV * cB; i += 64 * 256) {
            int bb = i >> 7;
            int vv = i & 127;
            d_xT[vv * cB + bb] = inputs[i];
        }
    }
}

// ==================================================================
// grid barrier (all GRID blocks resident).
// ==================================================================
__device__ __forceinline__ void grid_barrier() {
    __syncthreads();
    if (threadIdx.x == 0) {
        __threadfence();
        unsigned gen = d_bar_gen;
        unsigned t   = atomicAdd(&d_bar_count, 1u);
        if (t == GRID - 1) {
            d_bar_count = 0;
            __threadfence();
            d_bar_gen = gen + 1;
        } else {
            while (d_bar_gen == gen) { __nanosleep(64); }
        }
        __threadfence();
    }
    __syncthreads();
}

// ==================================================================
// PERSISTENT kernel: gather -> 4x (product, sum) -> root LSE.
// Product: em[e] = nm[c0]+nm[c1] (independent warp tasks).
// Sum: ONE em-row gather per f, shfl indices, depth-3 pipeline.
// ==================================================================
__global__ void __launch_bounds__(NT, BPSM) k_persist(const int* __restrict__ pc,
                                                      float* __restrict__ out) {
    __shared__ float4 s_m[NT];
    __shared__ float4 s_s[NT];
    const int t    = threadIdx.x;
    const int lane = t & 31;
    const int wid  = (blockIdx.x * NT + t) >> 5;   // global warp id

    // ---------- phase 0: input gather -> d_nmA ----------
    {
        const int stride = GRID * NT;
        for (int i = blockIdx.x * NT + t; i < cN * cB; i += stride) {
            int b  = i & (cB - 1);
            int vk = i >> 9;
            int v  = vk >> 5;
            int x  = d_xT[v * cB + b];
            d_nmA[i] = d_lwin[vk * cC + x];
        }
    }
    grid_barrier();

    // ---------- 4 layers ----------
    float* nm_src = d_nmA;
    float* nm_dst = d_nmB;
    for (int l = 0; l < cL; l++) {
        // ---- product phase: warp per (e, batch-quarter) ----
        const int2* pcl = reinterpret_cast<const int2*>(pc) + l * cE;
        {
            const float4* nmp = reinterpret_cast<const float4*>(nm_src);
            for (int task = wid; task < cE * 4; task += NWARP) {
                int e = task >> 2;
                int g = ((task & 3) << 5) + lane;
                int2 c = __ldg(pcl + e);
                float4 a = nmp[c.x * cB4 + g];
                float4 b = nmp[c.y * cB4 + g];
                float4 o;
                o.x = a.x + b.x; o.y = a.y + b.y;
                o.z = a.z + b.z; o.w = a.w + b.w;
                __stcg(reinterpret_cast<float4*>(d_em) + e * cB4 + g, o);
            }
        }
        grid_barrier();

        // ---- sum phase: warp per (n, quarter); one em row per f ----
        const int2* pwl = d_pw + l * cN * cF;
        {
            const float4* emp = reinterpret_cast<const float4*>(d_em);
            for (int task = wid; task < cN * 4; task += NWARP) {
                int n = task >> 2;
                int g = ((task & 3) << 5) + lane;
                // lane f (mirrored at f+16) owns table entry f
                int2 pm = __ldg(pwl + n * cF + (lane & 15));

                // f=0 (shift) + depth-3 slots (f=1..3): 4 gathers in flight
                float4 m  = emp[__shfl_sync(FULLM, pm.x, 0) + g];
                float4 xA = emp[__shfl_sync(FULLM, pm.x, 1) + g];
                float4 xB = emp[__shfl_sync(FULLM, pm.x, 2) + g];
                float4 xC = emp[__shfl_sync(FULLM, pm.x, 3) + g];

                float W0 = __uint_as_float(__shfl_sync(FULLM, (unsigned)pm.y, 0));
                float4 s = make_float4(W0, W0, W0, W0);

#pragma unroll
                for (int f = 1; f < cF; f++) {
                    float  W = __uint_as_float(__shfl_sync(FULLM, (unsigned)pm.y, f));
                    float4 x = xA;
                    xA = xB; xB = xC;
                    if (f + 3 < cF)    // prefetch f+3
                        xC = emp[__shfl_sync(FULLM, pm.x, f + 3) + g];
                    s.x += W * ex2(x.x - m.x);
                    s.y += W * ex2(x.y - m.y);
                    s.z += W * ex2(x.z - m.z);
                    s.w += W * ex2(x.w - m.w);
                }
                float4 o;
                o.x = m.x + lg2(s.x);
                o.y = m.y + lg2(s.y);
                o.z = m.z + lg2(s.z);
                o.w = m.w + lg2(s.w);
                __stcg(reinterpret_cast<float4*>(nm_dst) + n * cB4 + g, o);
            }
        }
        grid_barrier();

        float* tmp = nm_src; nm_src = nm_dst; nm_dst = tmp;
    }

    // ---------- root: out[b] = ln2 * (m + lg2(sum_n R_n 2^(x_nb - m))) ----------
    if (blockIdx.x < cB4) {
        const int g = blockIdx.x;              // float4 batch group
        const float4* nmp = reinterpret_cast<const float4*>(nm_src);

        float R0 = __ldg(d_R + t);
        float4 m = nmp[t * cB4 + g];
        float4 s = make_float4(R0, R0, R0, R0);
#pragma unroll
        for (int k = 1; k < cN / NT; k++) {
            int   n = t + k * NT;
            float R = __ldg(d_R + n);
            float4 x = nmp[n * cB4 + g];
            s.x += R * ex2(x.x - m.x);
            s.y += R * ex2(x.y - m.y);
            s.z += R * ex2(x.z - m.z);
            s.w += R * ex2(x.w - m.w);
        }
        s_m[t] = m; s_s[t] = s;
        __syncthreads();
        for (int o = NT / 2; o; o >>= 1) {
            if (t < o) {
                float4 m1 = s_m[t], m2 = s_m[t + o];
                float4 s1 = s_s[t], s2 = s_s[t + o];
                float4 mm, ss;
                mm.x = fmaxf(m1.x, m2.x);
                mm.y = fmaxf(m1.y, m2.y);
                mm.z = fmaxf(m1.z, m2.z);
                mm.w = fmaxf(m1.w, m2.w);
                ss.x = s1.x * ex2(m1.x - mm.x) + s2.x * ex2(m2.x - mm.x);
                ss.y = s1.y * ex2(m1.y - mm.y) + s2.y * ex2(m2.y - mm.y);
                ss.z = s1.z * ex2(m1.z - mm.z) + s2.z * ex2(m2.z - mm.z);
                ss.w = s1.w * ex2(m1.w - mm.w) + s2.w * ex2(m2.w - mm.w);
                s_m[t] = mm; s_s[t] = ss;
            }
            __syncthreads();
        }
        if (t == 0) {
            float4 m0 = s_m[0], s0 = s_s[0];
            out[g * 4 + 0] = (m0.x + lg2(s0.x)) * LN2F;
            out[g * 4 + 1] = (m0.y + lg2(s0.y)) * LN2F;
            out[g * 4 + 2] = (m0.z + lg2(s0.z)) * LN2F;
            out[g * 4 + 3] = (m0.w + lg2(s0.w)) * LN2F;
        }
    }
}

// ==================================================================
extern "C" void kernel_launch(void* const* d_in, const int* in_sizes, int n_in,
                              void* d_out, int out_size) {
    const int*   inputs = (const int*)d_in[0];    // (B, V)
    const int*   pc     = (const int*)d_in[1];    // (L, E, 2)
    const int*   sci    = (const int*)d_in[2];    // (L, N, F)
    const float* ip     = (const float*)d_in[3];  // (V, K, C)
    const float* sp     = (const float*)d_in[4];  // (L, N, F)
    const float* rp     = (const float*)d_in[5];  // (N,)
    float* out = (float*)d_out;                   // (B,)

    k_prep<<<641, 256>>>(ip, sp, rp, inputs, sci);
    k_persist<<<GRID, NT>>>(pc, out);
}